// round 9
// baseline (speedup 1.0000x reference)
#include <cuda_runtime.h>
#include <cstdint>
#include <cstddef>

#define Bn 8192
#define Tn 49
#define Cn 128
#define Hn 4
#define Dn 32
#define NWn 64
#define Mn (Bn*Tn)          // 401408

// ---------------- scratch (device globals: allocation-free rule) ----------------
__device__ float g_qkv[(size_t)3*Bn*Tn*Cn];   // [which][b][t][c], q pre-scaled
__device__ float g_bm[(size_t)NWn*Hn*Tn*Tn];  // bias+mask combined [w][h][t][s]

// ---------------- helpers ----------------
__device__ __forceinline__ unsigned f2tf_u(float x){
    unsigned r; asm("cvt.rna.tf32.f32 %0, %1;" : "=r"(r) : "f"(x)); return r;
}
__device__ __forceinline__ float f2tf(float x){ return __uint_as_float(f2tf_u(x)); }

__device__ __forceinline__ void mma8(float* c, const unsigned* a, const unsigned* b){
    asm volatile("mma.sync.aligned.m16n8k8.row.col.f32.tf32.tf32.f32 "
        "{%0,%1,%2,%3},{%4,%5,%6,%7},{%8,%9},{%0,%1,%2,%3};\n"
        : "+f"(c[0]), "+f"(c[1]), "+f"(c[2]), "+f"(c[3])
        : "r"(a[0]), "r"(a[1]), "r"(a[2]), "r"(a[3]), "r"(b[0]), "r"(b[1]));
}

// ---------------- kernel 0: combined bias+mask table ----------------
__global__ void bm_kernel(const float* __restrict__ bias_table,
                          const float* __restrict__ mask){
    int w = blockIdx.x, h = blockIdx.y;
    for (int i = threadIdx.x; i < Tn*Tn; i += blockDim.x){
        int t = i / Tn, s = i - (i / Tn) * Tn;
        int th = t / 7, tw = t % 7, sh = s / 7, sw = s % 7;
        int ridx = (th - sh + 6) * 13 + (tw - sw + 6);
        g_bm[(((size_t)w*Hn + h)*Tn + t)*Tn + s] =
            bias_table[ridx*Hn + h] + mask[((size_t)w*Tn + t)*Tn + s];
    }
}

// ---------------- kernel 1: QKV GEMM ----------------
// C[M,384] = x[M,128] @ qkv_w[384,128]^T + qkv_b ; scatter to g_qkv, q pre-scaled.
// A tile (256 rows) loaded ONCE; loops 3 n-tiles internally (W slices L2-resident).
#define GP 132   // smem pitch (floats); stride mod 32 = 4 -> conflict-free frags
__global__ __launch_bounds__(256,1)
void gemm_qkv(const float* __restrict__ A, const float* __restrict__ W,
              const float* __restrict__ bias){
    extern __shared__ float sm[];
    float* As = sm;              // 256 x 132
    float* Ws = sm + 256*GP;     // 128 x 132
    const int bm = blockIdx.x;
    const int tid = threadIdx.x;

    const float4* A4 = (const float4*)A;
    const size_t arow0 = (size_t)bm * 256;
    for (int i = tid; i < 256*32; i += 256){
        int r = i >> 5, c4 = i & 31;
        float4 v = A4[(arow0 + r)*32 + c4];
        float4 o; o.x=f2tf(v.x); o.y=f2tf(v.y); o.z=f2tf(v.z); o.w=f2tf(v.w);
        *(float4*)(As + r*GP + c4*4) = o;
    }

    const int warp = tid >> 5, lane = tid & 31, lq = lane >> 2, lr = lane & 3;
    const int m_base = (warp >> 1) * 64, n_base = (warp & 1) * 64;
    const float SCALE = 0.17677669529663687f;   // 32^-0.5
    const float4* W4 = (const float4*)W;

    for (int bn = 0; bn < 3; bn++){
        for (int i = tid; i < 128*32; i += 256){
            int r = i >> 5, c4 = i & 31;
            float4 v = W4[((size_t)bn*128 + r)*32 + c4];
            float4 o; o.x=f2tf(v.x); o.y=f2tf(v.y); o.z=f2tf(v.z); o.w=f2tf(v.w);
            *(float4*)(Ws + r*GP + c4*4) = o;
        }
        __syncthreads();

        float c[4][8][4];
        #pragma unroll
        for (int mi = 0; mi < 4; mi++)
            #pragma unroll
            for (int ni = 0; ni < 8; ni++)
                #pragma unroll
                for (int r = 0; r < 4; r++) c[mi][ni][r] = 0.f;

        #pragma unroll
        for (int k0 = 0; k0 < 128; k0 += 8){
            unsigned a[4][4], b[8][2];
            #pragma unroll
            for (int mi = 0; mi < 4; mi++){
                int r0 = m_base + mi*16 + lq;
                a[mi][0] = __float_as_uint(As[ r0   *GP + k0 + lr    ]);
                a[mi][1] = __float_as_uint(As[(r0+8)*GP + k0 + lr    ]);
                a[mi][2] = __float_as_uint(As[ r0   *GP + k0 + lr + 4]);
                a[mi][3] = __float_as_uint(As[(r0+8)*GP + k0 + lr + 4]);
            }
            #pragma unroll
            for (int ni = 0; ni < 8; ni++){
                int n0 = n_base + ni*8 + lq;
                b[ni][0] = __float_as_uint(Ws[n0*GP + k0 + lr    ]);
                b[ni][1] = __float_as_uint(Ws[n0*GP + k0 + lr + 4]);
            }
            #pragma unroll
            for (int mi = 0; mi < 4; mi++)
                #pragma unroll
                for (int ni = 0; ni < 8; ni++)
                    mma8(c[mi][ni], a[mi], b[ni]);
        }

        #pragma unroll
        for (int mi = 0; mi < 4; mi++){
            int rloc = m_base + mi*16 + lq;
            size_t gm0 = arow0 + rloc, gm1 = gm0 + 8;
            int b0i = (int)(gm0 / 49), t0 = (int)(gm0 - (size_t)b0i*49);
            int b1i = (int)(gm1 / 49), t1 = (int)(gm1 - (size_t)b1i*49);
            float sc = (bn == 0) ? SCALE : 1.0f;
            size_t base0 = (((size_t)bn*Bn + b0i)*Tn + t0)*Cn;
            size_t base1 = (((size_t)bn*Bn + b1i)*Tn + t1)*Cn;
            #pragma unroll
            for (int ni = 0; ni < 8; ni++){
                int col = n_base + ni*8 + lr*2;
                float bb0 = bias[bn*128 + col], bb1 = bias[bn*128 + col + 1];
                float2 v0 = make_float2((c[mi][ni][0]+bb0)*sc, (c[mi][ni][1]+bb1)*sc);
                float2 v1 = make_float2((c[mi][ni][2]+bb0)*sc, (c[mi][ni][3]+bb1)*sc);
                *(float2*)(g_qkv + base0 + col) = v0;
                *(float2*)(g_qkv + base1 + col) = v1;
            }
        }
        __syncthreads();   // protect Ws before next n-tile load
    }
}

// ---------------- kernel 2: fused attention + output projection ----------------
// Per window b: S = q k^T + (bias+mask); O = S v; out = O @ proj_w^T + proj_b.
// O head-stripes are written back into the q smem tile (lifetime-disjoint cols),
// then proj_w is staged into the dead k/v/S region for the final GEMM.
#define QP 132
#define SP 61
__global__ __launch_bounds__(256,2) void attn_kernel(
        const float* __restrict__ proj_w, const float* __restrict__ proj_b,
        float* __restrict__ out){
    extern __shared__ float sm[];
    float* qs = sm;               // 64 x 132 : q (rows>=49 zero); becomes O after use
    float* ks = qs + 64*QP;       // 56 x 132 : k (rows>=49 zero); later part of Pw
    float* vT = ks + 56*QP;       // 128 x 61 : vT[d][s] (s>=49 zero); later part of Pw
    float* Ss = vT + 128*SP;      // 64 x 61  : scores tile; later part of Pw
    float* Pw = ks;               // 128 x 132 proj weights (aliases ks+vT+Ss region)

    const int b = blockIdx.x;
    const int w = b & (NWn - 1);
    const int tid = threadIdx.x;
    const size_t bo = (size_t)b * (Tn*Cn);
    const float4* q4 = (const float4*)(g_qkv + bo);
    const float4* k4 = (const float4*)(g_qkv + (size_t)Bn*Tn*Cn + bo);
    const float*  vp = g_qkv + (size_t)2*Bn*Tn*Cn + bo;

    for (int i = tid; i < Tn*32; i += 256){
        int r = i >> 5, c4 = i & 31;
        float4 v = q4[i];
        float4 o; o.x=f2tf(v.x); o.y=f2tf(v.y); o.z=f2tf(v.z); o.w=f2tf(v.w);
        *(float4*)(qs + r*QP + c4*4) = o;
        float4 u = k4[i];
        float4 p; p.x=f2tf(u.x); p.y=f2tf(u.y); p.z=f2tf(u.z); p.w=f2tf(u.w);
        *(float4*)(ks + r*QP + c4*4) = p;
    }
    for (int i = tid; i < 15*QP; i += 256) qs[49*QP + i] = 0.f;
    for (int i = tid; i <  7*QP; i += 256) ks[49*QP + i] = 0.f;
    for (int i = tid; i < Tn*Cn; i += 256){
        int s = i >> 7, d = i & 127;
        vT[d*SP + s] = f2tf(vp[i]);
    }
    for (int i = tid; i < 128*12; i += 256){
        int d = i / 12, s = 49 + (i - d*12);
        vT[d*SP + s] = 0.f;
    }
    __syncthreads();

    const int warp = tid >> 5, lane = tid & 31, lq = lane >> 2, lr = lane & 3;
    const int mi = warp >> 1;          // row-tile owner: rows [mi*16, mi*16+16)
    const int r0 = mi*16 + lq;
    const int t0 = r0, t1 = r0 + 8;

    for (int h = 0; h < Hn; h++){
        // ---- stage 1: S = q_h k_h^T + (bias+mask) ----
        const int nh = warp & 1;
        const int ni0 = nh ? 4 : 0, nct = nh ? 3 : 4;

        // prefetch bias+mask values BEFORE the MMA chain (asm volatile mma8
        // blocks compiler hoisting; explicit early issue overlaps L2 latency
        // with the stage-1 tensor work)
        const size_t bmbase = (((size_t)w*Hn + h)*Tn)*Tn;
        float bmv[4][4];
        for (int j = 0; j < nct; j++){
            int ni = ni0 + j;
            int s0 = ni*8 + lr*2, s1 = s0 + 1;
            bmv[j][0] = (t0 < 49 && s0 < 49) ? g_bm[bmbase + t0*49 + s0] : 0.f;
            bmv[j][1] = (t0 < 49 && s1 < 49) ? g_bm[bmbase + t0*49 + s1] : 0.f;
            bmv[j][2] = (t1 < 49 && s0 < 49) ? g_bm[bmbase + t1*49 + s0] : 0.f;
            bmv[j][3] = (t1 < 49 && s1 < 49) ? g_bm[bmbase + t1*49 + s1] : 0.f;
        }

        float c1[4][4];
        #pragma unroll
        for (int j = 0; j < 4; j++){ c1[j][0]=0.f; c1[j][1]=0.f; c1[j][2]=0.f; c1[j][3]=0.f; }
        #pragma unroll
        for (int kk = 0; kk < 4; kk++){
            int k0 = h*32 + kk*8;
            unsigned a[4];
            a[0] = __float_as_uint(qs[ r0   *QP + k0 + lr    ]);
            a[1] = __float_as_uint(qs[(r0+8)*QP + k0 + lr    ]);
            a[2] = __float_as_uint(qs[ r0   *QP + k0 + lr + 4]);
            a[3] = __float_as_uint(qs[(r0+8)*QP + k0 + lr + 4]);
            for (int j = 0; j < nct; j++){
                int ni = ni0 + j;
                unsigned bb[2];
                bb[0] = __float_as_uint(ks[(ni*8+lq)*QP + k0 + lr    ]);
                bb[1] = __float_as_uint(ks[(ni*8+lq)*QP + k0 + lr + 4]);
                mma8(c1[j], a, bb);
            }
        }
        for (int j = 0; j < nct; j++){
            int ni = ni0 + j;
            int s0 = ni*8 + lr*2, s1 = s0 + 1;
            Ss[t0*SP + s0] = f2tf(c1[j][0] + bmv[j][0]);
            Ss[t0*SP + s1] = f2tf(c1[j][1] + bmv[j][1]);
            Ss[t1*SP + s0] = f2tf(c1[j][2] + bmv[j][2]);
            Ss[t1*SP + s1] = f2tf(c1[j][3] + bmv[j][3]);
        }
        __syncthreads();   // also orders: all stage-1 reads of qs cols h*32.. done

        // ---- stage 2: O_h = S v_h ; write into qs cols [h*32, h*32+32) ----
        const int dh = warp & 1;
        float c2[2][4];
        #pragma unroll
        for (int j = 0; j < 2; j++){ c2[j][0]=0.f; c2[j][1]=0.f; c2[j][2]=0.f; c2[j][3]=0.f; }
        #pragma unroll
        for (int kk = 0; kk < 7; kk++){
            int k0 = kk*8;
            unsigned a[4];
            a[0] = __float_as_uint(Ss[ r0   *SP + k0 + lr    ]);
            a[1] = __float_as_uint(Ss[(r0+8)*SP + k0 + lr    ]);
            a[2] = __float_as_uint(Ss[ r0   *SP + k0 + lr + 4]);
            a[3] = __float_as_uint(Ss[(r0+8)*SP + k0 + lr + 4]);
            #pragma unroll
            for (int j = 0; j < 2; j++){
                int nb = h*32 + (dh*2 + j)*8;
                unsigned bb[2];
                bb[0] = __float_as_uint(vT[(nb+lq)*SP + k0 + lr    ]);
                bb[1] = __float_as_uint(vT[(nb+lq)*SP + k0 + lr + 4]);
                mma8(c2[j], a, bb);
            }
        }
        #pragma unroll
        for (int j = 0; j < 2; j++){
            int ch = h*32 + (dh*2 + j)*8 + lr*2;
            if (t0 < 49){
                qs[t0*QP + ch    ] = f2tf(c2[j][0]);
                qs[t0*QP + ch + 1] = f2tf(c2[j][1]);
            }
            if (t1 < 49){
                qs[t1*QP + ch    ] = f2tf(c2[j][2]);
                qs[t1*QP + ch + 1] = f2tf(c2[j][3]);
            }
        }
        __syncthreads();   // O stripe visible; Ss/vT reads done before next head
    }

    // ---- stage 3: out = O @ proj_w^T + proj_b ----
    // qs now holds O[64][132] (rows>=49 zero). Stage proj_w over dead ks/vT/Ss.
    const float4* P4 = (const float4*)proj_w;
    for (int i = tid; i < 128*32; i += 256){
        int r = i >> 5, c4 = i & 31;
        float4 v = P4[(size_t)r*32 + c4];
        float4 o; o.x=f2tf(v.x); o.y=f2tf(v.y); o.z=f2tf(v.z); o.w=f2tf(v.w);
        *(float4*)(Pw + r*GP + c4*4) = o;
    }
    __syncthreads();

    {
        const int n_base = (warp & 1) * 64;
        float c[8][4];
        #pragma unroll
        for (int ni = 0; ni < 8; ni++){ c[ni][0]=0.f; c[ni][1]=0.f; c[ni][2]=0.f; c[ni][3]=0.f; }
        #pragma unroll
        for (int k0 = 0; k0 < 128; k0 += 8){
            unsigned a[4];
            a[0] = __float_as_uint(qs[ r0   *QP + k0 + lr    ]);
            a[1] = __float_as_uint(qs[(r0+8)*QP + k0 + lr    ]);
            a[2] = __float_as_uint(qs[ r0   *QP + k0 + lr + 4]);
            a[3] = __float_as_uint(qs[(r0+8)*QP + k0 + lr + 4]);
            #pragma unroll
            for (int ni = 0; ni < 8; ni++){
                int n0 = n_base + ni*8 + lq;
                unsigned bb[2];
                bb[0] = __float_as_uint(Pw[n0*GP + k0 + lr    ]);
                bb[1] = __float_as_uint(Pw[n0*GP + k0 + lr + 4]);
                mma8(c[ni], a, bb);
            }
        }
        const size_t orow = (size_t)b * Tn;
        #pragma unroll
        for (int ni = 0; ni < 8; ni++){
            int col = n_base + ni*8 + lr*2;
            float bb0 = proj_b[col], bb1 = proj_b[col + 1];
            if (t0 < 49)
                *(float2*)(out + (orow + t0)*Cn + col) = make_float2(c[ni][0]+bb0, c[ni][1]+bb1);
            if (t1 < 49)
                *(float2*)(out + (orow + t1)*Cn + col) = make_float2(c[ni][2]+bb0, c[ni][3]+bb1);
        }
    }
}

// ---------------- launch ----------------
extern "C" void kernel_launch(void* const* d_in, const int* in_sizes, int n_in,
                              void* d_out, int out_size){
    const float* x          = (const float*)d_in[0];
    const float* mask       = (const float*)d_in[1];
    const float* qkv_w      = (const float*)d_in[2];
    const float* qkv_b      = (const float*)d_in[3];
    const float* proj_w     = (const float*)d_in[4];
    const float* proj_b     = (const float*)d_in[5];
    const float* bias_table = (const float*)d_in[6];
    float* out = (float*)d_out;

    const int GEMM_SMEM = (256 + 128) * GP * 4;                  // 202752 B
    const int ATTN_SMEM = (64*QP + 56*QP + 128*SP + 64*SP) * 4;  // 110208 B
    cudaFuncSetAttribute(gemm_qkv, cudaFuncAttributeMaxDynamicSharedMemorySize, GEMM_SMEM);
    cudaFuncSetAttribute(attn_kernel, cudaFuncAttributeMaxDynamicSharedMemorySize, ATTN_SMEM);

    bm_kernel<<<dim3(NWn, Hn), 256>>>(bias_table, mask);
    gemm_qkv<<<Mn/256, 256, GEMM_SMEM>>>(x, qkv_w, qkv_b);
    attn_kernel<<<Bn, 256, ATTN_SMEM>>>(proj_w, proj_b, out);
}

// round 10
// speedup vs baseline: 1.5119x; 1.5119x over previous
#include <cuda_runtime.h>
#include <cuda_fp16.h>
#include <cstdint>
#include <cstddef>

#define Bn 8192
#define Tn 49
#define Cn 128
#define Hn 4
#define NWn 64
#define Mn (Bn*Tn)          // 401408

// ---------------- scratch (device globals; allocation-free rule) ----------------
__device__ __half g_qkv[(size_t)3*Bn*Tn*Cn];  // [which][b][t][c] fp16, q pre-scaled
__device__ float  g_bm[(size_t)NWn*Hn*Tn*Tn]; // bias+mask combined [w][h][t][s]

// ---------------- helpers ----------------
// m16n8k16 fp16 mma, fp32 accumulate
__device__ __forceinline__ void mma16(float* c, const unsigned* a, const unsigned* b){
    asm volatile("mma.sync.aligned.m16n8k16.row.col.f32.f16.f16.f32 "
        "{%0,%1,%2,%3},{%4,%5,%6,%7},{%8,%9},{%0,%1,%2,%3};\n"
        : "+f"(c[0]), "+f"(c[1]), "+f"(c[2]), "+f"(c[3])
        : "r"(a[0]), "r"(a[1]), "r"(a[2]), "r"(a[3]), "r"(b[0]), "r"(b[1]));
}

// ---------------- kernel 0: combined bias+mask table ----------------
__global__ void bm_kernel(const float* __restrict__ bias_table,
                          const float* __restrict__ mask){
    int w = blockIdx.x, h = blockIdx.y;
    for (int i = threadIdx.x; i < Tn*Tn; i += blockDim.x){
        int t = i / Tn, s = i - (i / Tn) * Tn;
        int th = t / 7, tw = t % 7, sh = s / 7, sw = s % 7;
        int ridx = (th - sh + 6) * 13 + (tw - sw + 6);
        g_bm[(((size_t)w*Hn + h)*Tn + t)*Tn + s] =
            bias_table[ridx*Hn + h] + mask[((size_t)w*Tn + t)*Tn + s];
    }
}

// ---------------- kernel 1: QKV GEMM (fp16 mma) ----------------
// C[M,384] = x[M,128] @ qkv_w[384,128]^T + qkv_b ; fp16 scatter to g_qkv, q scaled.
// 128x128 CTA tile; A loaded once; 3 n-tiles looped (W slices L2-resident).
#define AP 68   // half2 pitch (68 mod 32 == 4 -> conflict-free fragment loads)
__global__ __launch_bounds__(256,2)
void gemm_qkv(const float* __restrict__ A, const float* __restrict__ W,
              const float* __restrict__ bias){
    extern __shared__ __half2 smh[];
    __half2* As = smh;            // 128 x 68 half2 (=128x136 halfs, 128 data cols)
    __half2* Ws = smh + 128*AP;   // 128 x 68
    const unsigned* AsU = (const unsigned*)As;
    const unsigned* WsU = (const unsigned*)Ws;
    const int bm = blockIdx.x, tid = threadIdx.x;

    const float4* A4 = (const float4*)A;
    const size_t arow0 = (size_t)bm * 128;
    for (int i = tid; i < 128*32; i += 256){
        int r = i >> 5, c4 = i & 31;
        float4 v = A4[(arow0 + r)*32 + c4];
        As[r*AP + c4*2    ] = __floats2half2_rn(v.x, v.y);
        As[r*AP + c4*2 + 1] = __floats2half2_rn(v.z, v.w);
    }

    const int warp = tid >> 5, lane = tid & 31, lq = lane >> 2, lr = lane & 3;
    const int m_base = (warp >> 1) * 32, n_base = (warp & 1) * 64;
    const float SCALE = 0.17677669529663687f;   // 32^-0.5
    const float4* W4 = (const float4*)W;

    for (int bn = 0; bn < 3; bn++){
        for (int i = tid; i < 128*32; i += 256){
            int r = i >> 5, c4 = i & 31;
            float4 v = W4[((size_t)bn*128 + r)*32 + c4];
            Ws[r*AP + c4*2    ] = __floats2half2_rn(v.x, v.y);
            Ws[r*AP + c4*2 + 1] = __floats2half2_rn(v.z, v.w);
        }
        __syncthreads();

        float c[2][8][4];
        #pragma unroll
        for (int mi = 0; mi < 2; mi++)
            #pragma unroll
            for (int ni = 0; ni < 8; ni++)
                #pragma unroll
                for (int r = 0; r < 4; r++) c[mi][ni][r] = 0.f;

        #pragma unroll
        for (int k2 = 0; k2 < 64; k2 += 8){       // k2 = k/2 (half2 units), K=16/iter
            unsigned a[2][4], b[8][2];
            #pragma unroll
            for (int mi = 0; mi < 2; mi++){
                int r0 = m_base + mi*16 + lq;
                a[mi][0] = AsU[ r0   *AP + k2 + lr    ];
                a[mi][1] = AsU[(r0+8)*AP + k2 + lr    ];
                a[mi][2] = AsU[ r0   *AP + k2 + lr + 4];
                a[mi][3] = AsU[(r0+8)*AP + k2 + lr + 4];
            }
            #pragma unroll
            for (int ni = 0; ni < 8; ni++){
                int n0 = n_base + ni*8 + lq;
                b[ni][0] = WsU[n0*AP + k2 + lr    ];
                b[ni][1] = WsU[n0*AP + k2 + lr + 4];
            }
            #pragma unroll
            for (int mi = 0; mi < 2; mi++)
                #pragma unroll
                for (int ni = 0; ni < 8; ni++)
                    mma16(c[mi][ni], a[mi], b[ni]);
        }

        #pragma unroll
        for (int mi = 0; mi < 2; mi++){
            int rloc = m_base + mi*16 + lq;
            size_t gm0 = arow0 + rloc, gm1 = gm0 + 8;
            int b0i = (int)(gm0 / 49), t0 = (int)(gm0 - (size_t)b0i*49);
            int b1i = (int)(gm1 / 49), t1 = (int)(gm1 - (size_t)b1i*49);
            float sc = (bn == 0) ? SCALE : 1.0f;
            size_t base0 = (((size_t)bn*Bn + b0i)*Tn + t0)*Cn;
            size_t base1 = (((size_t)bn*Bn + b1i)*Tn + t1)*Cn;
            #pragma unroll
            for (int ni = 0; ni < 8; ni++){
                int col = n_base + ni*8 + lr*2;
                float bb0 = bias[bn*128 + col], bb1 = bias[bn*128 + col + 1];
                *(__half2*)(g_qkv + base0 + col) =
                    __floats2half2_rn((c[mi][ni][0]+bb0)*sc, (c[mi][ni][1]+bb1)*sc);
                *(__half2*)(g_qkv + base1 + col) =
                    __floats2half2_rn((c[mi][ni][2]+bb0)*sc, (c[mi][ni][3]+bb1)*sc);
            }
        }
        __syncthreads();   // protect Ws before next n-tile load
    }
}

// ---------------- kernel 2: fused attention + output projection (fp16 mma) ------
// Per window b: S = q k^T + (bias+mask); O = S v; out = O @ proj_w^T + proj_b.
#define QP2 68   // qs/ks/Pw pitch in half2 (mod 32 == 4)
#define VP2 36   // vT pitch in half2 (s packed in pairs; 32 data + 4 pad)
#define SP2 36   // Ss pitch in half2
__global__ __launch_bounds__(256,2) void attn_kernel(
        const float* __restrict__ proj_w, const float* __restrict__ proj_b,
        float* __restrict__ out){
    extern __shared__ __half2 smh[];
    __half2* qs = smh;              // 64 x 68 : q rows (>=49 zero); becomes O
    __half2* ks = qs + 64*QP2;      // 56 x 68 : k rows (>=49 zero); later Pw part
    __half2* vT = ks + 56*QP2;      // 128 x 36: vT[d][s-pair] (s>=49 zero); later Pw
    __half2* Ss = vT + 128*VP2;     // 64 x 36 : scores (s-pairs; pad cols zero)
    __half2* Pw = ks;               // 128 x 68 proj weights (aliases ks+vT+Ss)
    const unsigned* qsU = (const unsigned*)qs;
    const unsigned* ksU = (const unsigned*)ks;
    const unsigned* vTU = (const unsigned*)vT;
    const unsigned* SsU = (const unsigned*)Ss;
    const unsigned* PwU = (const unsigned*)Pw;

    const int b = blockIdx.x;
    const int w = b & (NWn - 1);
    const int tid = threadIdx.x;
    const size_t bo = (size_t)b * (Tn*Cn);
    const unsigned* qh2 = (const unsigned*)(g_qkv + bo);
    const unsigned* kh2 = (const unsigned*)(g_qkv + (size_t)Bn*Tn*Cn + bo);
    const __half*   vh  = g_qkv + (size_t)2*Bn*Tn*Cn + bo;

    // q/k tiles: rows of 64 half2 (coalesced 4B loads)
    for (int i = tid; i < Tn*64; i += 256){
        int r = i >> 6, c2 = i & 63;
        qs[r*QP2 + c2] = *(const __half2*)&qh2[i];
        ks[r*QP2 + c2] = *(const __half2*)&kh2[i];
    }
    const __half2 z2 = __floats2half2_rn(0.f, 0.f);
    for (int i = tid; i < 15*QP2; i += 256) qs[49*QP2 + i] = z2;
    for (int i = tid; i <  7*QP2; i += 256) ks[49*QP2 + i] = z2;
    // vT transpose: pair tokens (2*t2, 2*t2+1) per channel d
    for (int i = tid; i < 28*128; i += 256){
        int t2 = i >> 7, d = i & 127;
        int s0 = 2*t2, s1 = 2*t2 + 1;
        __half h0 = (s0 < Tn) ? vh[s0*Cn + d] : __float2half(0.f);
        __half h1 = (s1 < Tn) ? vh[s1*Cn + d] : __float2half(0.f);
        vT[d*VP2 + t2] = __halves2half2(h0, h1);
    }
    for (int i = tid; i < 128*8; i += 256){       // vT pad cols t2=28..35
        int d = i >> 3, t2 = 28 + (i & 7);
        vT[d*VP2 + t2] = z2;
    }
    for (int i = tid; i < 64*8; i += 256){        // Ss pad cols 28..35 (never rewritten)
        int r = i >> 3, c = 28 + (i & 7);
        Ss[r*SP2 + c] = z2;
    }
    __syncthreads();

    const int warp = tid >> 5, lane = tid & 31, lq = lane >> 2, lr = lane & 3;
    const int mi = warp >> 1;          // row-tile owner: rows [mi*16, mi*16+16)
    const int r0 = mi*16 + lq;
    const int t0 = r0, t1 = r0 + 8;

    for (int h = 0; h < Hn; h++){
        // ---- stage 1: S = q_h k_h^T + (bias+mask) ----
        const int nh = warp & 1;
        const int ni0 = nh ? 4 : 0, nct = nh ? 3 : 4;

        const size_t bmbase = (((size_t)w*Hn + h)*Tn)*Tn;
        float bmv[4][4];
        for (int j = 0; j < nct; j++){
            int ni = ni0 + j;
            int s0 = ni*8 + lr*2, s1 = s0 + 1;
            bmv[j][0] = (t0 < 49 && s0 < 49) ? g_bm[bmbase + t0*49 + s0] : 0.f;
            bmv[j][1] = (t0 < 49 && s1 < 49) ? g_bm[bmbase + t0*49 + s1] : 0.f;
            bmv[j][2] = (t1 < 49 && s0 < 49) ? g_bm[bmbase + t1*49 + s0] : 0.f;
            bmv[j][3] = (t1 < 49 && s1 < 49) ? g_bm[bmbase + t1*49 + s1] : 0.f;
        }

        float c1[4][4];
        #pragma unroll
        for (int j = 0; j < 4; j++){ c1[j][0]=0.f; c1[j][1]=0.f; c1[j][2]=0.f; c1[j][3]=0.f; }
        #pragma unroll
        for (int kk = 0; kk < 2; kk++){           // head K=32 -> two K=16 steps
            int k2 = h*16 + kk*8;
            unsigned a[4];
            a[0] = qsU[ r0   *QP2 + k2 + lr    ];
            a[1] = qsU[(r0+8)*QP2 + k2 + lr    ];
            a[2] = qsU[ r0   *QP2 + k2 + lr + 4];
            a[3] = qsU[(r0+8)*QP2 + k2 + lr + 4];
            for (int j = 0; j < nct; j++){
                int ni = ni0 + j;
                unsigned bb[2];
                bb[0] = ksU[(ni*8+lq)*QP2 + k2 + lr    ];
                bb[1] = ksU[(ni*8+lq)*QP2 + k2 + lr + 4];
                mma16(c1[j], a, bb);
            }
        }
        for (int j = 0; j < nct; j++){
            int ni = ni0 + j;
            Ss[t0*SP2 + ni*4 + lr] = __floats2half2_rn(c1[j][0]+bmv[j][0], c1[j][1]+bmv[j][1]);
            Ss[t1*SP2 + ni*4 + lr] = __floats2half2_rn(c1[j][2]+bmv[j][2], c1[j][3]+bmv[j][3]);
        }
        __syncthreads();

        // ---- stage 2: O_h = S v_h ; write into qs cols [h*32, h*32+32) ----
        const int dh = warp & 1;
        float c2[2][4];
        #pragma unroll
        for (int j = 0; j < 2; j++){ c2[j][0]=0.f; c2[j][1]=0.f; c2[j][2]=0.f; c2[j][3]=0.f; }
        #pragma unroll
        for (int kk = 0; kk < 4; kk++){           // s padded to 64 -> four K=16 steps
            int k2 = kk*8;
            unsigned a[4];
            a[0] = SsU[ r0   *SP2 + k2 + lr    ];
            a[1] = SsU[(r0+8)*SP2 + k2 + lr    ];
            a[2] = SsU[ r0   *SP2 + k2 + lr + 4];
            a[3] = SsU[(r0+8)*SP2 + k2 + lr + 4];
            #pragma unroll
            for (int j = 0; j < 2; j++){
                int nb = h*32 + (dh*2 + j)*8;
                unsigned bb[2];
                bb[0] = vTU[(nb+lq)*VP2 + k2 + lr    ];
                bb[1] = vTU[(nb+lq)*VP2 + k2 + lr + 4];
                mma16(c2[j], a, bb);
            }
        }
        #pragma unroll
        for (int j = 0; j < 2; j++){
            int ch2 = (h*32 + (dh*2 + j)*8)/2 + lr;   // half2 column index
            if (t0 < 49) qs[t0*QP2 + ch2] = __floats2half2_rn(c2[j][0], c2[j][1]);
            if (t1 < 49) qs[t1*QP2 + ch2] = __floats2half2_rn(c2[j][2], c2[j][3]);
        }
        __syncthreads();
    }

    // ---- stage 3: out = O @ proj_w^T + proj_b ----
    const float4* P4 = (const float4*)proj_w;
    for (int i = tid; i < 128*32; i += 256){
        int r = i >> 5, c4 = i & 31;
        float4 v = P4[(size_t)r*32 + c4];
        Pw[r*QP2 + c4*2    ] = __floats2half2_rn(v.x, v.y);
        Pw[r*QP2 + c4*2 + 1] = __floats2half2_rn(v.z, v.w);
    }
    __syncthreads();

    {
        const int n_base = (warp & 1) * 64;
        float c[8][4];
        #pragma unroll
        for (int ni = 0; ni < 8; ni++){ c[ni][0]=0.f; c[ni][1]=0.f; c[ni][2]=0.f; c[ni][3]=0.f; }
        #pragma unroll
        for (int k2 = 0; k2 < 64; k2 += 8){
            unsigned a[4];
            a[0] = qsU[ r0   *QP2 + k2 + lr    ];
            a[1] = qsU[(r0+8)*QP2 + k2 + lr    ];
            a[2] = qsU[ r0   *QP2 + k2 + lr + 4];
            a[3] = qsU[(r0+8)*QP2 + k2 + lr + 4];
            #pragma unroll
            for (int ni = 0; ni < 8; ni++){
                int n0 = n_base + ni*8 + lq;
                unsigned bb[2];
                bb[0] = PwU[n0*QP2 + k2 + lr    ];
                bb[1] = PwU[n0*QP2 + k2 + lr + 4];
                mma16(c[ni], a, bb);
            }
        }
        const size_t orow = (size_t)b * Tn;
        #pragma unroll
        for (int ni = 0; ni < 8; ni++){
            int col = n_base + ni*8 + lr*2;
            float bb0 = proj_b[col], bb1 = proj_b[col + 1];
            if (t0 < 49)
                *(float2*)(out + (orow + t0)*Cn + col) = make_float2(c[ni][0]+bb0, c[ni][1]+bb1);
            if (t1 < 49)
                *(float2*)(out + (orow + t1)*Cn + col) = make_float2(c[ni][2]+bb0, c[ni][3]+bb1);
        }
    }
}

// ---------------- launch ----------------
extern "C" void kernel_launch(void* const* d_in, const int* in_sizes, int n_in,
                              void* d_out, int out_size){
    const float* x          = (const float*)d_in[0];
    const float* mask       = (const float*)d_in[1];
    const float* qkv_w      = (const float*)d_in[2];
    const float* qkv_b      = (const float*)d_in[3];
    const float* proj_w     = (const float*)d_in[4];
    const float* proj_b     = (const float*)d_in[5];
    const float* bias_table = (const float*)d_in[6];
    float* out = (float*)d_out;

    const int GEMM_SMEM = 2 * 128 * AP * 4;                          // 69632 B
    const int ATTN_SMEM = (64*QP2 + 56*QP2 + 128*VP2 + 64*SP2) * 4;  // 60288 B
    cudaFuncSetAttribute(gemm_qkv, cudaFuncAttributeMaxDynamicSharedMemorySize, GEMM_SMEM);
    cudaFuncSetAttribute(attn_kernel, cudaFuncAttributeMaxDynamicSharedMemorySize, ATTN_SMEM);

    bm_kernel<<<dim3(NWn, Hn), 256>>>(bias_table, mask);
    gemm_qkv<<<Mn/128, 256, GEMM_SMEM>>>(x, qkv_w, qkv_b);
    attn_kernel<<<Bn, 256, ATTN_SMEM>>>(proj_w, proj_b, out);
}